// round 15
// baseline (speedup 1.0000x reference)
#include <cuda_runtime.h>
#include <math.h>
#include <stdint.h>

#define BB 8
#define TT 1024
#define CC 192
#define HH 2
#define DKK 96
#define FCC 768
#define LL 6
#define WW 4

// ---------------- scratch (device globals; no allocations) ----------------
__device__ float g_X [BB*CC*TT];
__device__ float g_Q [BB*CC*TT];
__device__ float g_K [BB*CC*TT];
__device__ float g_V [BB*CC*TT];
__device__ float g_A [BB*CC*TT];
__device__ float g_Y [BB*CC*TT];
__device__ float g_RL[BB*HH*TT*9];
__device__ float g_S [(size_t)BB*HH*TT*TT];   // band-added scores
__device__ float g_PM[BB*HH*TT*8];            // per-(row, s-chunk) max
__device__ float g_PS[BB*HH*TT*8];            // per-(row, s-chunk) sumexp
__device__ float g_Hf[BB*FCC*TT];
__device__ float g_W1t[LL*3*FCC*CC];          // pre-rounded, [l][j][f][c]
__device__ float g_W2t[LL*3*CC*FCC];

static __device__ __forceinline__ float relscale() { return 0.10206207261596577f; } // 1/sqrt(96)

static __device__ __forceinline__ uint32_t f2tf(float f) {
    uint32_t r;
    asm("cvt.rna.tf32.f32 %0, %1;" : "=r"(r) : "f"(f));
    return r;
}
static __device__ __forceinline__ uint4 cvt4(float4 v) {
    uint4 u; u.x = f2tf(v.x); u.y = f2tf(v.y); u.z = f2tf(v.z); u.w = f2tf(v.w); return u;
}

static __device__ __forceinline__ void mma8(float* c, const uint32_t* a, const uint32_t* b) {
    asm volatile(
        "mma.sync.aligned.m16n8k8.row.col.f32.tf32.tf32.f32 "
        "{%0,%1,%2,%3},{%4,%5,%6,%7},{%8,%9},{%0,%1,%2,%3};"
        : "+f"(c[0]), "+f"(c[1]), "+f"(c[2]), "+f"(c[3])
        : "r"(a[0]), "r"(a[1]), "r"(a[2]), "r"(a[3]), "r"(b[0]), "r"(b[1]));
}

static __device__ __forceinline__ void cpa16(void* s, const void* g) {
    uint32_t sa = (uint32_t)__cvta_generic_to_shared(s);
    asm volatile("cp.async.cg.shared.global [%0], [%1], 16;" :: "r"(sa), "l"(g));
}
#define CP_COMMIT asm volatile("cp.async.commit_group;")
#define CP_WAIT0  asm volatile("cp.async.wait_group 0;")

// ----- stage over one BK=32 chunk; A smem [m][k], B smem [k][n] ------------
template<int MI, int NI>
static __device__ __forceinline__ void stage_mk_kn(
    const uint32_t* sA, int lda, const uint32_t* sB, int ldb, int nofs,
    float (*acc)[NI][4], int wm, int wn, int grp, int qid)
{
#pragma unroll
    for (int ks = 0; ks < 32; ks += 8) {
        uint32_t a[MI][4], b[NI][2];
#pragma unroll
        for (int mi = 0; mi < MI; mi++) {
            const uint32_t* p0 = sA + (wm + mi*16 + grp)*lda + ks + qid;
            a[mi][0] = p0[0]; a[mi][1] = p0[8*lda]; a[mi][2] = p0[4]; a[mi][3] = p0[8*lda + 4];
        }
#pragma unroll
        for (int ni = 0; ni < NI; ni++) {
            const uint32_t* q0 = sB + (ks + qid)*ldb + nofs + wn + ni*8 + grp;
            b[ni][0] = q0[0]; b[ni][1] = q0[4*ldb];
        }
#pragma unroll
        for (int mi = 0; mi < MI; mi++)
#pragma unroll
            for (int ni = 0; ni < NI; ni++)
                mma8(acc[mi][ni], a[mi], b[ni]);
    }
}

// ----- A smem [k][m], B smem [k][n] ----------------------------------------
template<int MI, int NI>
static __device__ __forceinline__ void stage_km_kn(
    const uint32_t* sA, int lda, const uint32_t* sB, int ldb,
    float (*acc)[NI][4], int wm, int wn, int grp, int qid)
{
#pragma unroll
    for (int ks = 0; ks < 32; ks += 8) {
        uint32_t a[MI][4], b[NI][2];
#pragma unroll
        for (int mi = 0; mi < MI; mi++) {
            const uint32_t* p0 = sA + (ks + qid)*lda + wm + mi*16 + grp;
            const uint32_t* p1 = p0 + 4*lda;
            a[mi][0] = p0[0]; a[mi][1] = p0[8]; a[mi][2] = p1[0]; a[mi][3] = p1[8];
        }
#pragma unroll
        for (int ni = 0; ni < NI; ni++) {
            const uint32_t* q0 = sB + (ks + qid)*ldb + wn + ni*8 + grp;
            b[ni][0] = q0[0]; b[ni][1] = q0[4*ldb];
        }
#pragma unroll
        for (int mi = 0; mi < MI; mi++)
#pragma unroll
            for (int ni = 0; ni < NI; ni++)
                mma8(acc[mi][ni], a[mi], b[ni]);
    }
}

// ----- A smem [m][k], B smem [n][k] ----------------------------------------
template<int MI, int NI>
static __device__ __forceinline__ void stage_mk_nk(
    const uint32_t* sA, int lda, const uint32_t* sB, int ldb,
    float (*acc)[NI][4], int wm, int wn, int grp, int qid)
{
#pragma unroll
    for (int ks = 0; ks < 32; ks += 8) {
        uint32_t a[MI][4], b[NI][2];
#pragma unroll
        for (int mi = 0; mi < MI; mi++) {
            const uint32_t* p0 = sA + (wm + mi*16 + grp)*lda + ks + qid;
            a[mi][0] = p0[0]; a[mi][1] = p0[8*lda]; a[mi][2] = p0[4]; a[mi][3] = p0[8*lda + 4];
        }
#pragma unroll
        for (int ni = 0; ni < NI; ni++) {
            const uint32_t* q0 = sB + (wn + ni*8 + grp)*ldb + ks + qid;
            b[ni][0] = q0[0]; b[ni][1] = q0[4];
        }
#pragma unroll
        for (int mi = 0; mi < MI; mi++)
#pragma unroll
            for (int ni = 0; ni < NI; ni++)
                mma8(acc[mi][ni], a[mi], b[ni]);
    }
}

// ===== projection body (double-buffered, cvt fills) ========================
#define PROJ_SMEM_W (2*64*36 + 2*32*136)
static __device__ __forceinline__ void proj_body(
    const float* __restrict__ W, const float* __restrict__ bias,
    const float* __restrict__ Xb, float* __restrict__ Ob, int o0, int n0,
    uint32_t* sm)
{
    uint32_t* sA = sm;
    uint32_t* sB = sm + 2*64*36;
    const int tid = threadIdx.x;
    const int lane = tid & 31, w = tid >> 5;
    const int grp = lane >> 2, qid = lane & 3;
    const int wm = (w & 1)*32, wn = (w >> 1)*32;
    float acc[2][4][4] = {};
    const int rA = tid >> 3,  cA = (tid & 7)*4;
    const int rB = tid >> 5,  cB = (tid & 31)*4;

#pragma unroll
    for (int jj = 0; jj < 2; jj++) {
        float4 v = *(const float4*)&W[(o0 + rA + jj*32)*CC + cA];
        *(uint4*)&sA[(rA + jj*32)*36 + cA] = cvt4(v);
    }
#pragma unroll
    for (int jj = 0; jj < 4; jj++) {
        float4 v = *(const float4*)&Xb[(size_t)(rB + jj*8)*TT + n0 + cB];
        *(uint4*)&sB[(rB + jj*8)*136 + cB] = cvt4(v);
    }
    __syncthreads();

    const int NK = CC/32;
    for (int k = 0; k < NK; k++) {
        float4 ra[2], rb[4];
        if (k + 1 < NK) {
            int k0 = (k + 1)*32;
#pragma unroll
            for (int jj = 0; jj < 2; jj++)
                ra[jj] = *(const float4*)&W[(o0 + rA + jj*32)*CC + k0 + cA];
#pragma unroll
            for (int jj = 0; jj < 4; jj++)
                rb[jj] = *(const float4*)&Xb[(size_t)(k0 + rB + jj*8)*TT + n0 + cB];
        }
        int cur = k & 1;
        stage_mk_kn<2,4>(sA + cur*64*36, 36, sB + cur*32*136, 136, 0, acc, wm, wn, grp, qid);
        if (k + 1 < NK) {
            int nx = cur ^ 1;
#pragma unroll
            for (int jj = 0; jj < 2; jj++)
                *(uint4*)&sA[nx*64*36 + (rA + jj*32)*36 + cA] = cvt4(ra[jj]);
#pragma unroll
            for (int jj = 0; jj < 4; jj++)
                *(uint4*)&sB[nx*32*136 + (rB + jj*8)*136 + cB] = cvt4(rb[jj]);
            __syncthreads();
        }
    }
#pragma unroll
    for (int mi = 0; mi < 2; mi++) {
        int r0 = o0 + wm + mi*16 + grp;
        float bb0 = bias[r0], bb1 = bias[r0 + 8];
#pragma unroll
        for (int ni = 0; ni < 4; ni++) {
            int c0 = n0 + wn + ni*8 + qid*2;
            Ob[(size_t)r0*TT + c0]       = acc[mi][ni][0] + bb0;
            Ob[(size_t)r0*TT + c0 + 1]   = acc[mi][ni][1] + bb0;
            Ob[(size_t)(r0+8)*TT + c0]   = acc[mi][ni][2] + bb1;
            Ob[(size_t)(r0+8)*TT + c0+1] = acc[mi][ni][3] + bb1;
        }
    }
}

__global__ void qkv_mma(const float* __restrict__ Wq, const float* __restrict__ bq,
                        const float* __restrict__ Wk, const float* __restrict__ bk,
                        const float* __restrict__ Wv, const float* __restrict__ bv,
                        const float* __restrict__ X,
                        float* __restrict__ Qo, float* __restrict__ Ko, float* __restrict__ Vo)
{
    extern __shared__ uint32_t sm[];
    const int sel = blockIdx.x / 3;
    const int o0  = (blockIdx.x % 3)*64;
    const int n0  = blockIdx.y*128;
    const int b   = blockIdx.z;
    const float* W    = (sel == 0) ? Wq : (sel == 1) ? Wk : Wv;
    const float* bias = (sel == 0) ? bq : (sel == 1) ? bk : bv;
    float* Out        = (sel == 0) ? Qo : (sel == 1) ? Ko : Vo;
    proj_body(W, bias, X + (size_t)b*CC*TT, Out + (size_t)b*CC*TT, o0, n0, sm);
}

__global__ void proj_mma(const float* __restrict__ W, const float* __restrict__ bias,
                         const float* __restrict__ X, float* __restrict__ Out)
{
    extern __shared__ uint32_t sm[];
    proj_body(W, bias, X + (size_t)blockIdx.z*CC*TT, Out + (size_t)blockIdx.z*CC*TT,
              blockIdx.x*64, blockIdx.y*128, sm);
}

// ------- rel logits (coalesced thread-per-t, 64-thread blocks) -------------
__global__ void rel_logits_k(const float* __restrict__ Q, const float* __restrict__ erk)
{
    const int bh = blockIdx.y, b = bh / HH, h = bh % HH;
    const int t = blockIdx.x*64 + threadIdx.x;
    __shared__ float sE[9*96];
    for (int i = threadIdx.x; i < 9*96; i += 64) sE[i] = erk[i];
    __syncthreads();
    const float* q = Q + (size_t)(b*CC + h*DKK)*TT;
    float acc[9] = {};
#pragma unroll 4
    for (int d = 0; d < DKK; d++) {
        float qv = q[(size_t)d*TT + t];
#pragma unroll
        for (int m = 0; m < 9; m++) acc[m] += qv * sE[m*96 + d];
    }
    float* out = g_RL + ((size_t)bh*TT + t)*9;
    const float sc = relscale();
#pragma unroll
    for (int m = 0; m < 9; m++) out[m] = acc[m]*sc;
}

// ===== scores: S[t,s] = (q*sc)·k + band; writes S + per-chunk (max,sumexp) =
#define SCORES_SMEM_W (2*32*72 + 2*32*136 + 576 + 256 + 256)
__global__ void scores_mma(const float* __restrict__ Q, const float* __restrict__ Kk)
{
    extern __shared__ uint32_t sm[];
    uint32_t* sA = sm;
    uint32_t* sB = sm + 2*32*72;
    float* sRL = (float*)(sm + 2*32*72 + 2*32*136);   // [64][9]
    float* sMx = sRL + 576;                            // [64][4]
    float* sSm = sMx + 256;                            // [64][4]
    const int bh = blockIdx.z, b = bh >> 1, h = bh & 1;
    const float* q = Q  + (size_t)(b*CC + h*DKK)*TT;
    const float* k = Kk + (size_t)(b*CC + h*DKK)*TT;
    float* S = g_S + (size_t)bh*TT*TT;
    const int t0 = blockIdx.x*64, s0 = blockIdx.y*128;
    const int sy = blockIdx.y;

    const int tid = threadIdx.x;
    const int lane = tid & 31, w = tid >> 5;
    const int grp = lane >> 2, qid = lane & 3;
    const int wm = (w & 1)*32, wn = (w >> 1)*32;
    const int wnid = w >> 1;
    const float sc = relscale();
    float acc[2][4][4] = {};
    const int rA = tid >> 4, cA = (tid & 15)*4;
    const int rB = tid >> 5, cB = (tid & 31)*4;

    // band logits for this t block (contiguous copy)
    const float* rlg = g_RL + ((size_t)bh*TT + t0)*9;
    for (int i = tid; i < 576; i += 256) sRL[i] = rlg[i];

    auto ldq = [&](int k0, int jj) {
        float4 v = *(const float4*)&q[(size_t)(k0 + rA + jj*16)*TT + t0 + cA];
        v.x *= sc; v.y *= sc; v.z *= sc; v.w *= sc;
        return v;
    };
#pragma unroll
    for (int jj = 0; jj < 2; jj++)
        *(uint4*)&sA[(rA + jj*16)*72 + cA] = cvt4(ldq(0, jj));
#pragma unroll
    for (int jj = 0; jj < 4; jj++) {
        float4 v = *(const float4*)&k[(size_t)(rB + jj*8)*TT + s0 + cB];
        *(uint4*)&sB[(rB + jj*8)*136 + cB] = cvt4(v);
    }
    __syncthreads();

    const int NK = DKK/32;
    for (int kc = 0; kc < NK; kc++) {
        float4 ra[2], rb[4];
        if (kc + 1 < NK) {
            int k0 = (kc + 1)*32;
#pragma unroll
            for (int jj = 0; jj < 2; jj++) ra[jj] = ldq(k0, jj);
#pragma unroll
            for (int jj = 0; jj < 4; jj++)
                rb[jj] = *(const float4*)&k[(size_t)(k0 + rB + jj*8)*TT + s0 + cB];
        }
        int cur = kc & 1;
        stage_km_kn<2,4>(sA + cur*32*72, 72, sB + cur*32*136, 136, acc, wm, wn, grp, qid);
        if (kc + 1 < NK) {
            int nx = cur ^ 1;
#pragma unroll
            for (int jj = 0; jj < 2; jj++)
                *(uint4*)&sA[nx*32*72 + (rA + jj*16)*72 + cA] = cvt4(ra[jj]);
#pragma unroll
            for (int jj = 0; jj < 4; jj++)
                *(uint4*)&sB[nx*32*136 + (rB + jj*8)*136 + cB] = cvt4(rb[jj]);
            __syncthreads();
        }
    }

    // ---- epilogue: band add + store + per-row chunk (max, sumexp) ----
    float vv[2][4][4];
#pragma unroll
    for (int mi = 0; mi < 2; mi++) {
        int rl0 = wm + mi*16 + grp;      // local rows rl0, rl0+8
        int rl1 = rl0 + 8;
#pragma unroll
        for (int ni = 0; ni < 4; ni++) {
            int cl = wn + ni*8 + qid*2;
            int sg = s0 + cl;
#pragma unroll
            for (int e = 0; e < 2; e++) {
                float v0 = acc[mi][ni][e];
                int off0 = sg + e - (t0 + rl0);
                if (off0 >= -WW && off0 <= WW) v0 += sRL[rl0*9 + off0 + WW];
                vv[mi][ni][e] = v0;
                float v1 = acc[mi][ni][2 + e];
                int off1 = sg + e - (t0 + rl1);
                if (off1 >= -WW && off1 <= WW) v1 += sRL[rl1*9 + off1 + WW];
                vv[mi][ni][2 + e] = v1;
            }
            S[(size_t)(t0 + rl0)*TT + sg]     = vv[mi][ni][0];
            S[(size_t)(t0 + rl0)*TT + sg + 1] = vv[mi][ni][1];
            S[(size_t)(t0 + rl1)*TT + sg]     = vv[mi][ni][2];
            S[(size_t)(t0 + rl1)*TT + sg + 1] = vv[mi][ni][3];
        }
    }
    // per-row max over this thread's 8 cols, then over qid, then across warps
    float mx[2][2];
#pragma unroll
    for (int mi = 0; mi < 2; mi++) {
        mx[mi][0] = -1e30f; mx[mi][1] = -1e30f;
#pragma unroll
        for (int ni = 0; ni < 4; ni++) {
            mx[mi][0] = fmaxf(mx[mi][0], fmaxf(vv[mi][ni][0], vv[mi][ni][1]));
            mx[mi][1] = fmaxf(mx[mi][1], fmaxf(vv[mi][ni][2], vv[mi][ni][3]));
        }
#pragma unroll
        for (int r = 0; r < 2; r++) {
            mx[mi][r] = fmaxf(mx[mi][r], __shfl_xor_sync(0xffffffffu, mx[mi][r], 1));
            mx[mi][r] = fmaxf(mx[mi][r], __shfl_xor_sync(0xffffffffu, mx[mi][r], 2));
        }
    }
    if (qid == 0) {
#pragma unroll
        for (int mi = 0; mi < 2; mi++) {
            sMx[(wm + mi*16 + grp)*4 + wnid]     = mx[mi][0];
            sMx[(wm + mi*16 + grp + 8)*4 + wnid] = mx[mi][1];
        }
    }
    __syncthreads();
    float gs[2][2] = {};
#pragma unroll
    for (int mi = 0; mi < 2; mi++) {
        int rl0 = wm + mi*16 + grp;
        float m0 = fmaxf(fmaxf(sMx[rl0*4], sMx[rl0*4+1]), fmaxf(sMx[rl0*4+2], sMx[rl0*4+3]));
        float m1 = fmaxf(fmaxf(sMx[(rl0+8)*4], sMx[(rl0+8)*4+1]),
                         fmaxf(sMx[(rl0+8)*4+2], sMx[(rl0+8)*4+3]));
#pragma unroll
        for (int ni = 0; ni < 4; ni++) {
            gs[mi][0] += __expf(vv[mi][ni][0] - m0) + __expf(vv[mi][ni][1] - m0);
            gs[mi][1] += __expf(vv[mi][ni][2] - m1) + __expf(vv[mi][ni][3] - m1);
        }
#pragma unroll
        for (int r = 0; r < 2; r++) {
            gs[mi][r] += __shfl_xor_sync(0xffffffffu, gs[mi][r], 1);
            gs[mi][r] += __shfl_xor_sync(0xffffffffu, gs[mi][r], 2);
        }
    }
    if (qid == 0) {
#pragma unroll
        for (int mi = 0; mi < 2; mi++) {
            sSm[(wm + mi*16 + grp)*4 + wnid]     = gs[mi][0];
            sSm[(wm + mi*16 + grp + 8)*4 + wnid] = gs[mi][1];
        }
    }
    __syncthreads();
    if (tid < 64) {
        float m = fmaxf(fmaxf(sMx[tid*4], sMx[tid*4+1]), fmaxf(sMx[tid*4+2], sMx[tid*4+3]));
        float s = sSm[tid*4] + sSm[tid*4+1] + sSm[tid*4+2] + sSm[tid*4+3];
        size_t base = ((size_t)bh*TT + t0 + tid)*8 + sy;
        g_PM[base] = m;
        g_PS[base] = s;
    }
}

// ===== attn out: softmax-on-the-fly + PV + rel-v band; 96(d) x 128(t) =====
#define ATTN_SMEM_W (2*96*36 + 2*128*36 + 128*9 + 9*96 + 128 + 128)
__global__ void attnout_mma(const float* __restrict__ V, const float* __restrict__ erv)
{
    extern __shared__ uint32_t sm[];
    uint32_t* sA  = sm;                      // 2 * 96*36, [m=d][k=s]
    uint32_t* sB  = sm + 2*96*36;            // 2 * 128*36, [n=t][k=s]
    float*    sPb = (float*)(sm + 2*96*36 + 2*128*36);   // [128][9]
    float*    sE  = sPb + 128*9;                          // [9][96]
    float*    sMx = sE + 864;                             // [128]
    float*    sIv = sMx + 128;                            // [128]
    const int bh = blockIdx.y, b = bh >> 1, h = bh & 1;
    const float* p = g_S + (size_t)bh*TT*TT;
    const float* v = V   + (size_t)(b*CC + h*DKK)*TT;
    float*       a = g_A + (size_t)(b*CC + h*DKK)*TT;
    const int t0 = blockIdx.x*128;

    const int tid = threadIdx.x;
    const int lane = tid & 31, w = tid >> 5;
    const int grp = lane >> 2, qid = lane & 3;
    const int wm = (w & 1)*48, wn = (w >> 1)*32;
    float acc[3][4][4] = {};
    const int rT = tid >> 3, cT = (tid & 7)*4;

    // row stats: combine 8 chunk partials
    if (tid < 128) {
        size_t base = ((size_t)bh*TT + t0 + tid)*8;
        float pm[8], ps[8];
        float m = -1e30f;
#pragma unroll
        for (int j = 0; j < 8; j++) { pm[j] = g_PM[base + j]; ps[j] = g_PS[base + j]; m = fmaxf(m, pm[j]); }
        float s = 0.f;
#pragma unroll
        for (int j = 0; j < 8; j++) s += ps[j]*__expf(pm[j] - m);
        sMx[tid] = m;
        sIv[tid] = 1.f / s;
    }
    __syncthreads();

    auto pxf = [&](float4 s4, int row) {
        float mxv = sMx[row], iv = sIv[row];
        uint4 u;
        u.x = f2tf(__expf(s4.x - mxv)*iv);
        u.y = f2tf(__expf(s4.y - mxv)*iv);
        u.z = f2tf(__expf(s4.z - mxv)*iv);
        u.w = f2tf(__expf(s4.w - mxv)*iv);
        return u;
    };

    // band P + erv (once)
    for (int i = tid; i < 128*9; i += 256) {
        int tr = i / 9, m = i - tr*9;
        int s = t0 + tr + m - WW;
        sPb[tr*9 + m] = (s >= 0 && s < TT)
            ? __expf(p[(size_t)(t0 + tr)*TT + s] - sMx[tr])*sIv[tr] : 0.f;
    }
    for (int i = tid; i < 9*96; i += 256) sE[i] = erv[i];

#pragma unroll
    for (int jj = 0; jj < 3; jj++) {
        float4 vvv = *(const float4*)&v[(size_t)(rT + jj*32)*TT + cT];
        *(uint4*)&sA[(rT + jj*32)*36 + cT] = cvt4(vvv);
    }
#pragma unroll
    for (int jj = 0; jj < 4; jj++) {
        float4 pv = *(const float4*)&p[(size_t)(t0 + rT + jj*32)*TT + cT];
        *(uint4*)&sB[(rT + jj*32)*36 + cT] = pxf(pv, rT + jj*32);
    }
    __syncthreads();

    const int NK = TT/32;  // 32
    for (int kc = 0; kc < NK; kc++) {
        float4 ra[3], rb[4];
        if (kc + 1 < NK) {
            int s0 = (kc + 1)*32;
#pragma unroll
            for (int jj = 0; jj < 3; jj++)
                ra[jj] = *(const float4*)&v[(size_t)(rT + jj*32)*TT + s0 + cT];
#pragma unroll
            for (int jj = 0; jj < 4; jj++)
                rb[jj] = *(const float4*)&p[(size_t)(t0 + rT + jj*32)*TT + s0 + cT];
        }
        int cur = kc & 1;
        stage_mk_nk<3,4>(sA + cur*96*36, 36, sB + cur*128*36, 36, acc, wm, wn, grp, qid);
        if (kc + 1 < NK) {
            int nx = cur ^ 1;
#pragma unroll
            for (int jj = 0; jj < 3; jj++)
                *(uint4*)&sA[nx*96*36 + (rT + jj*32)*36 + cT] = cvt4(ra[jj]);
#pragma unroll
            for (int jj = 0; jj < 4; jj++)
                *(uint4*)&sB[nx*128*36 + (rT + jj*32)*36 + cT] = pxf(rb[jj], rT + jj*32);
            __syncthreads();
        }
    }
    // epilogue: add banded rel-v term and store
#pragma unroll
    for (int mi = 0; mi < 3; mi++) {
        int r0 = wm + mi*16 + grp;           // d rows r0, r0+8
        float e0[9], e1[9];
#pragma unroll
        for (int m = 0; m < 9; m++) { e0[m] = sE[m*96 + r0]; e1[m] = sE[m*96 + r0 + 8]; }
#pragma unroll
        for (int ni = 0; ni < 4; ni++) {
            int cl = wn + ni*8 + qid*2;      // local t
            float s00 = 0.f, s01 = 0.f, s10 = 0.f, s11 = 0.f;
#pragma unroll
            for (int m = 0; m < 9; m++) {
                float p0 = sPb[cl*9 + m], p1 = sPb[(cl+1)*9 + m];
                s00 += p0*e0[m]; s01 += p1*e0[m];
                s10 += p0*e1[m]; s11 += p1*e1[m];
            }
            int c0 = t0 + cl;
            a[(size_t)r0*TT + c0]       = acc[mi][ni][0] + s00;
            a[(size_t)r0*TT + c0 + 1]   = acc[mi][ni][1] + s01;
            a[(size_t)(r0+8)*TT + c0]   = acc[mi][ni][2] + s10;
            a[(size_t)(r0+8)*TT + c0+1] = acc[mi][ni][3] + s11;
        }
    }
}

// ===== conv3 v2 (conv1 only): 128(f) x 128(t), cp.async weights ============
#define CONV1_SMEM_W (2*3*128*36 + 2*32*136)
__global__ void __launch_bounds__(256, 1)
conv3_mma_128(const float* __restrict__ Wt, const float* __restrict__ bias,
              const float* __restrict__ X, float* __restrict__ Out,
              int Cout, int Cin, int do_relu)
{
    extern __shared__ uint32_t sm[];
    uint32_t* sA = sm;                 // 2 × 3 × 128*36
    uint32_t* sB = sm + 2*3*128*36;    // 2 × 32*136 slab; col = t - t0 + 4
    const int o0 = blockIdx.x*128, t0 = blockIdx.y*128, b = blockIdx.z;
    const float* Xb = X + (size_t)b*Cin*TT;
    float* Ob = Out + (size_t)b*Cout*TT;

    const int tid = threadIdx.x;
    const int lane = tid & 31, w = tid >> 5;
    const int grp = lane >> 2, qid = lane & 3;
    const int wm = (w & 3)*32, wn = (w >> 2)*64;
    float acc[2][8][4] = {};
    const int rS = tid >> 5, cS = (tid & 31)*4;
    const int er = tid >> 1, es = tid & 1;

    auto fill_slab = [&](uint32_t* dst, int c0) {
#pragma unroll
        for (int jj = 0; jj < 4; jj++) {
            float4 v = *(const float4*)&Xb[(size_t)(c0 + rS + jj*8)*TT + t0 + cS];
            *(uint4*)&dst[(rS + jj*8)*136 + 4 + cS] = cvt4(v);
        }
        if (tid < 64) {
            int t = es ? (t0 + 128) : (t0 - 1);
            int col = es ? 132 : 3;
            float vv = (t >= 0 && t < TT) ? Xb[(size_t)(c0 + er)*TT + t] : 0.f;
            dst[er*136 + col] = f2tf(vv);
        }
    };
    auto cpa_w = [&](uint32_t* dst, int c0) {
#pragma unroll
        for (int jj = 0; jj < 12; jj++) {
            int i = tid + jj*256;
            int j = i >> 10, r = (i >> 3) & 127, c4 = (i & 7)*4;
            cpa16(&dst[j*128*36 + r*36 + c4],
                  &Wt[((size_t)j*Cout + o0 + r)*Cin + c0 + c4]);
        }
    };

    cpa_w(sA, 0); CP_COMMIT;
    fill_slab(sB, 0);
    CP_WAIT0;
    __syncthreads();

    const int NK = Cin/32;
    for (int kc = 0; kc < NK; kc++) {
        int cur = kc & 1, nx = cur ^ 1;
        float4 rx[4]; float re = 0.f;
        if (kc + 1 < NK) {
            int c0 = (kc + 1)*32;
            cpa_w(sA + nx*3*128*36, c0);       // async, overlaps mma below
            CP_COMMIT;
#pragma unroll
            for (int jj = 0; jj < 4; jj++)
                rx[jj] = *(const float4*)&Xb[(size_t)(c0 + rS + jj*8)*TT + t0 + cS];
            if (tid < 64) {
                int t = es ? (t0 + 128) : (t0 - 1);
                re = (t >= 0 && t < TT) ? Xb[(size_t)(c0 + er)*TT + t] : 0.f;
            }
        }
#pragma unroll
        for (int j = 0; j < 3; j++)
            stage_mk_kn<2,8>(sA + cur*3*128*36 + j*128*36, 36, sB + cur*32*136, 136,
                             j + 3, acc, wm, wn, grp, qid);
        if (kc + 1 < NK) {
#pragma unroll
            for (int jj = 0; jj < 4; jj++)
                *(uint4*)&sB[nx*32*136 + (rS + jj*8)*136 + 4 + cS] = cvt4(rx[jj]);
            if (tid < 64) {
                int col = es ? 132 : 3;
                sB[nx*32*136 + er*136 + col] = f2tf(re);
            }
            CP_WAIT0;
            __syncthreads();
        }
    }
#pragma unroll
    for (int mi = 0; mi < 2; mi++) {
        int r0 = o0 + wm + mi*16 + grp;
        float bb0 = bias[r0], bb1 = bias[r0 + 8];
#pragma unroll
        for (int ni = 0; ni < 8; ni++) {
            int c0 = t0 + wn + ni*8 + qid*2;
            float v0 = acc[mi][ni][0] + bb0;
            float v1 = acc[mi][ni][1] + bb0;
            float v2 = acc[mi][ni][2] + bb1;
            float v3 = acc[mi][ni][3] + bb1;
            if (do_relu) { v0 = fmaxf(v0, 0.f); v1 = fmaxf(v1, 0.f);
                           v2 = fmaxf(v2, 0.f); v3 = fmaxf(v3, 0.f); }
            Ob[(size_t)r0*TT + c0]       = v0;
            Ob[(size_t)r0*TT + c0 + 1]   = v1;
            Ob[(size_t)(r0+8)*TT + c0]   = v2;
            Ob[(size_t)(r0+8)*TT + c0+1] = v3;
        }
    }
}

// ===== conv3 (DB): 64(f) x 128(t) — used for conv2 =========================
#define CONV_SMEM_W (2*3*64*36 + 2*32*136)
__global__ void conv3_mma(const float* __restrict__ Wt, const float* __restrict__ bias,
                          const float* __restrict__ X, float* __restrict__ Out,
                          int Cout, int Cin, int do_relu)
{
    extern __shared__ uint32_t sm[];
    uint32_t* sA = sm;                 // 2 * 3 * 64*36
    uint32_t* sB = sm + 2*3*64*36;     // 2 * 32*136 slab; col = t - t0 + 4
    const int o0 = blockIdx.x*64, t0 = blockIdx.y*128, b = blockIdx.z;
    const float* Xb = X + (size_t)b*Cin*TT;
    float* Ob = Out + (size_t)b*Cout*TT;

    const int tid = threadIdx.x;
    const int lane = tid & 31, w = tid >> 5;
    const int grp = lane >> 2, qid = lane & 3;
    const int wm = (w & 1)*32, wn = (w >> 1)*32;
    float acc[2][4][4] = {};
    const int rS = tid >> 5, cS = (tid & 31)*4;
    const int er = tid >> 1, es = tid & 1;

    auto fill_slab = [&](uint32_t* dst, int c0) {
#pragma unroll
        for (int jj = 0; jj < 4; jj++) {
            float4 v = *(const float4*)&Xb[(size_t)(c0 + rS + jj*8)*TT + t0 + cS];
            *(uint4*)&dst[(rS + jj*8)*136 + 4 + cS] = cvt4(v);
        }
        if (tid < 64) {
            int t = es ? (t0 + 128) : (t0 - 1);
            int col = es ? 132 : 3;
            float vv = (t >= 0 && t < TT) ? Xb[(size_t)(c0 + er)*TT + t] : 0.f;
            dst[er*136 + col] = f2tf(vv);
        }
    };
    auto fill_w = [&](uint32_t* dst, int c0) {
#pragma unroll
        for (int jj = 0; jj < 6; jj++) {
            int i = tid + jj*256;
            int j = i >> 9, r = (i >> 3) & 63, c4 = (i & 7)*4;
            *(uint4*)&dst[j*2304 + r*36 + c4] =
                *(const uint4*)&Wt[((size_t)j*Cout + o0 + r)*Cin + c0 + c4];
        }
    };

    fill_slab(sB, 0);
    fill_w(sA, 0);
    __syncthreads();

    const int NK = Cin/32;
    for (int kc = 0; kc < NK; kc++) {
        float4 rx[4]; float re = 0.f; uint4 rw[6];
        if (kc + 1 < NK) {
            int c0 = (kc + 1)*32;
#pragma unroll
            for (int jj = 0; jj < 4; jj++)
                rx[jj] = *(const float4*)&Xb[(size_t)(c0 + rS + jj*8)*TT + t0 + cS];
            if (tid < 64) {
                int t = es ? (t0 + 128) : (t0 - 1);
                re = (t >= 0 && t < TT) ? Xb[(size_t)(c0 + er)*TT + t] : 0.f;
            }
#pragma unroll
            for (int jj = 0; jj < 6; jj++) {
                int i = tid + jj*256;
                int j = i >> 9, r = (i >> 3) & 63, c4 = (i & 7)*4;
                rw[jj] = *(const uint4*)&Wt[((size_t)j*Cout + o0 + r)*Cin + c0 + c4];
            }
        }
        int cur = kc & 1;
#pragma unroll
        for (int j = 0; j < 3; j++)
            stage_mk_kn<2,4>(sA + cur*3*2304 + j*2304, 36, sB + cur*32*136, 136,
                             j + 3, acc, wm, wn, grp, qid);
        if (kc + 1 < NK) {
            int nx = cur ^ 1;
#pragma unroll
            for (int jj = 0; jj < 4; jj++)
                *(uint4*)&sB[nx*32*136 + (rS + jj*8)*136 + 4 + cS] = cvt4(rx[jj]);
            if (tid < 64) {
                int col = es ? 132 : 3;
                sB[nx*32*136 + er*136 + col] = f2tf(re);
            }
#pragma unroll
            for (int jj = 0; jj < 6; jj++) {
                int i = tid + jj*256;
                int j = i >> 9, r = (i >> 3) & 63, c4 = (i & 7)*4;
                *(uint4*)&sA[nx*3*2304 + j*2304 + r*36 + c4] = rw[jj];
            }
            __syncthreads();
        }
    }
#pragma unroll
    for (int mi = 0; mi < 2; mi++) {
        int r0 = o0 + wm + mi*16 + grp;
        float bb0 = bias[r0], bb1 = bias[r0 + 8];
#pragma unroll
        for (int ni = 0; ni < 4; ni++) {
            int c0 = t0 + wn + ni*8 + qid*2;
            float v0 = acc[mi][ni][0] + bb0;
            float v1 = acc[mi][ni][1] + bb0;
            float v2 = acc[mi][ni][2] + bb1;
            float v3 = acc[mi][ni][3] + bb1;
            if (do_relu) { v0 = fmaxf(v0, 0.f); v1 = fmaxf(v1, 0.f);
                           v2 = fmaxf(v2, 0.f); v3 = fmaxf(v3, 0.f); }
            Ob[(size_t)r0*TT + c0]       = v0;
            Ob[(size_t)r0*TT + c0 + 1]   = v1;
            Ob[(size_t)(r0+8)*TT + c0]   = v2;
            Ob[(size_t)(r0+8)*TT + c0+1] = v3;
        }
    }
}

// ---- weight transpose+round: wt[l][j][f][c] = tf32(w[l][f][c][j]) ----------
__global__ void round_transpose_w(const float* __restrict__ w, float* __restrict__ wt,
                                  int Cout, int Cin)
{
    int idx = blockIdx.x*256 + threadIdx.x;
    int per = Cout*Cin*3;
    if (idx >= LL*per) return;
    int l = idx / per;
    int rem = idx - l*per;
    int j = rem / (Cout*Cin);
    int r2 = rem - j*Cout*Cin;
    int f = r2 / Cin, c = r2 - f*Cin;
    wt[idx] = __uint_as_float(f2tf(w[((size_t)l*Cout*Cin + (size_t)f*Cin + c)*3 + j]));
}

// --------- add + channel LayerNorm: Out = LN_c(X+Y)*g + beta ---------------
__global__ void add_ln_k(const float* __restrict__ X, const float* __restrict__ Y,
                         const float* __restrict__ g, const float* __restrict__ be,
                         float* __restrict__ Out)
{
    int idx = blockIdx.x*blockDim.x + threadIdx.x;
    if (idx >= BB*TT) return;
    int b = idx / TT, t = idx % TT;
    const float* xp = X + (size_t)b*CC*TT + t;
    const float* yp = Y + (size_t)b*CC*TT + t;
    float s = 0.f, sq = 0.f;
#pragma unroll 8
    for (int c = 0; c < CC; c++) {
        float v = xp[(size_t)c*TT] + yp[(size_t)c*TT];
        s += v; sq += v*v;
    }
    const float invC = 1.f / CC;
    float mean = s*invC;
    float var  = sq*invC - mean*mean;
    float rstd = rsqrtf(var + 1e-5f);
    float* op = Out + (size_t)b*CC*TT + t;
#pragma unroll 8
    for (int c = 0; c < CC; c++) {
        float v = xp[(size_t)c*TT] + yp[(size_t)c*TT];
        op[(size_t)c*TT] = (v - mean)*rstd*g[c] + be[c];
    }
}

// ---------------------------- host orchestration ---------------------------
extern "C" void kernel_launch(void* const* d_in, const int* in_sizes, int n_in,
                              void* d_out, int out_size)
{
    (void)in_sizes; (void)n_in; (void)out_size;
    const float* x_in = (const float*)d_in[0];
    const float* Wq = (const float*)d_in[2];
    const float* bq = (const float*)d_in[3];
    const float* Wk = (const float*)d_in[4];
    const float* bk = (const float*)d_in[5];
    const float* Wv = (const float*)d_in[6];
    const float* bv = (const float*)d_in[7];
    const float* Wo = (const float*)d_in[8];
    const float* bo = (const float*)d_in[9];
    const float* erk = (const float*)d_in[10];
    const float* erv = (const float*)d_in[11];
    const float* ln1g = (const float*)d_in[12];
    const float* ln1b = (const float*)d_in[13];
    const float* w1 = (const float*)d_in[14];
    const float* b1 = (const float*)d_in[15];
    const float* w2 = (const float*)d_in[16];
    const float* b2 = (const float*)d_in[17];
    const float* ln2g = (const float*)d_in[18];
    const float* ln2b = (const float*)d_in[19];

    float *X, *Q, *K, *V, *A, *Y, *W1t, *W2t, *Hf;
    cudaGetSymbolAddress((void**)&X,  g_X);
    cudaGetSymbolAddress((void**)&Q,  g_Q);
    cudaGetSymbolAddress((void**)&K,  g_K);
    cudaGetSymbolAddress((void**)&V,  g_V);
    cudaGetSymbolAddress((void**)&A,  g_A);
    cudaGetSymbolAddress((void**)&Y,  g_Y);
    cudaGetSymbolAddress((void**)&W1t, g_W1t);
    cudaGetSymbolAddress((void**)&W2t, g_W2t);
    cudaGetSymbolAddress((void**)&Hf, g_Hf);

    const int PROJ_SMEM   = PROJ_SMEM_W*4;
    const int SCORES_SMEM = SCORES_SMEM_W*4;
    const int ATTN_SMEM   = ATTN_SMEM_W*4;
    const int CONV_SMEM   = CONV_SMEM_W*4;
    const int CONV1_SMEM  = CONV1_SMEM_W*4;
    cudaFuncSetAttribute(qkv_mma,    cudaFuncAttributeMaxDynamicSharedMemorySize, PROJ_SMEM);
    cudaFuncSetAttribute(proj_mma,   cudaFuncAttributeMaxDynamicSharedMemorySize, PROJ_SMEM);
    cudaFuncSetAttribute(scores_mma, cudaFuncAttributeMaxDynamicSharedMemorySize, SCORES_SMEM);
    cudaFuncSetAttribute(attnout_mma,cudaFuncAttributeMaxDynamicSharedMemorySize, ATTN_SMEM);
    cudaFuncSetAttribute(conv3_mma,  cudaFuncAttributeMaxDynamicSharedMemorySize, CONV_SMEM);
    cudaFuncSetAttribute(conv3_mma_128, cudaFuncAttributeMaxDynamicSharedMemorySize, CONV1_SMEM);

    // one-time weight transpose + tf32 pre-round
    {
        int tot1 = LL*FCC*CC*3;
        round_transpose_w<<<(tot1 + 255)/256, 256>>>(w1, W1t, FCC, CC);
        int tot2 = LL*CC*FCC*3;
        round_transpose_w<<<(tot2 + 255)/256, 256>>>(w2, W2t, CC, FCC);
    }

    const dim3 gqkv(9, TT/128, BB);
    const dim3 gproj(CC/64, TT/128, BB);
    const dim3 gscore(TT/64, TT/128, BB*HH);
    const dim3 grel(TT/64, BB*HH);
    const dim3 gao(TT/128, BB*HH);
    const dim3 gc1(FCC/128, TT/128, BB);
    const dim3 gc2(CC/64, TT/128, BB);
    const int lnBlocks = (BB*TT + 255)/256;

    for (int i = 0; i < LL; i++) {
        const float* xcur = (i == 0) ? x_in : X;
        qkv_mma<<<gqkv, 256, PROJ_SMEM>>>(Wq + (size_t)i*CC*CC, bq + i*CC,
                                          Wk + (size_t)i*CC*CC, bk + i*CC,
                                          Wv + (size_t)i*CC*CC, bv + i*CC,
                                          xcur, Q, K, V);
        rel_logits_k<<<grel, 64>>>(Q, erk + (size_t)i*9*DKK);
        scores_mma<<<gscore, 256, SCORES_SMEM>>>(Q, K);
        attnout_mma<<<gao, 256, ATTN_SMEM>>>(V, erv + (size_t)i*9*DKK);
        proj_mma<<<gproj, 256, PROJ_SMEM>>>(Wo + (size_t)i*CC*CC, bo + i*CC, A, Y);
        add_ln_k<<<lnBlocks, 256>>>(xcur, Y, ln1g + i*CC, ln1b + i*CC, X);
        conv3_mma_128<<<gc1, 256, CONV1_SMEM>>>(W1t + (size_t)i*3*FCC*CC, b1 + i*FCC,
                                                X, Hf, FCC, CC, 1);
        conv3_mma<<<gc2, 256, CONV_SMEM>>>(W2t + (size_t)i*3*CC*FCC, b2 + i*CC,
                                           Hf, Y, CC, FCC, 0);
        add_ln_k<<<lnBlocks, 256>>>(X, Y, ln2g + i*CC, ln2b + i*CC,
                                    (i == LL-1) ? (float*)d_out : X);
    }
}

// round 16
// speedup vs baseline: 1.0877x; 1.0877x over previous
#include <cuda_runtime.h>
#include <math.h>
#include <stdint.h>

#define BB 8
#define TT 1024
#define CC 192
#define HH 2
#define DKK 96
#define FCC 768
#define LL 6
#define WW 4

// ---------------- scratch (device globals; no allocations) ----------------
__device__ float g_X [BB*CC*TT];
__device__ float g_Q [BB*CC*TT];
__device__ float g_K [BB*CC*TT];
__device__ float g_V [BB*CC*TT];
__device__ float g_A [BB*CC*TT];
__device__ float g_Y [BB*CC*TT];
__device__ float g_RL[BB*HH*TT*9];
__device__ float g_S [(size_t)BB*HH*TT*TT];   // band-added scores
__device__ float g_PM[BB*HH*TT*8];            // per-(row, s-chunk) max
__device__ float g_PS[BB*HH*TT*8];            // per-(row, s-chunk) sumexp
__device__ float g_Hf[BB*FCC*TT];
__device__ float g_W1t[LL*3*FCC*CC];          // pre-rounded, [l][j][f][c]
__device__ float g_W2t[LL*3*CC*FCC];

static __device__ __forceinline__ float relscale() { return 0.10206207261596577f; } // 1/sqrt(96)

static __device__ __forceinline__ uint32_t f2tf(float f) {
    uint32_t r;
    asm("cvt.rna.tf32.f32 %0, %1;" : "=r"(r) : "f"(f));
    return r;
}
static __device__ __forceinline__ uint4 cvt4(float4 v) {
    uint4 u; u.x = f2tf(v.x); u.y = f2tf(v.y); u.z = f2tf(v.z); u.w = f2tf(v.w); return u;
}

static __device__ __forceinline__ void mma8(float* c, const uint32_t* a, const uint32_t* b) {
    asm volatile(
        "mma.sync.aligned.m16n8k8.row.col.f32.tf32.tf32.f32 "
        "{%0,%1,%2,%3},{%4,%5,%6,%7},{%8,%9},{%0,%1,%2,%3};"
        : "+f"(c[0]), "+f"(c[1]), "+f"(c[2]), "+f"(c[3])
        : "r"(a[0]), "r"(a[1]), "r"(a[2]), "r"(a[3]), "r"(b[0]), "r"(b[1]));
}

static __device__ __forceinline__ void cpa16(void* s, const void* g) {
    uint32_t sa = (uint32_t)__cvta_generic_to_shared(s);
    asm volatile("cp.async.cg.shared.global [%0], [%1], 16;" :: "r"(sa), "l"(g));
}
#define CP_COMMIT asm volatile("cp.async.commit_group;")
#define CP_WAIT0  asm volatile("cp.async.wait_group 0;")

// ----- stage over one BK=32 chunk; A smem [m][k], B smem [k][n] ------------
template<int MI, int NI>
static __device__ __forceinline__ void stage_mk_kn(
    const uint32_t* sA, int lda, const uint32_t* sB, int ldb, int nofs,
    float (*acc)[NI][4], int wm, int wn, int grp, int qid)
{
#pragma unroll
    for (int ks = 0; ks < 32; ks += 8) {
        uint32_t a[MI][4], b[NI][2];
#pragma unroll
        for (int mi = 0; mi < MI; mi++) {
            const uint32_t* p0 = sA + (wm + mi*16 + grp)*lda + ks + qid;
            a[mi][0] = p0[0]; a[mi][1] = p0[8*lda]; a[mi][2] = p0[4]; a[mi][3] = p0[8*lda + 4];
        }
#pragma unroll
        for (int ni = 0; ni < NI; ni++) {
            const uint32_t* q0 = sB + (ks + qid)*ldb + nofs + wn + ni*8 + grp;
            b[ni][0] = q0[0]; b[ni][1] = q0[4*ldb];
        }
#pragma unroll
        for (int mi = 0; mi < MI; mi++)
#pragma unroll
            for (int ni = 0; ni < NI; ni++)
                mma8(acc[mi][ni], a[mi], b[ni]);
    }
}

// ----- A smem [k][m], B smem [k][n] ----------------------------------------
template<int MI, int NI>
static __device__ __forceinline__ void stage_km_kn(
    const uint32_t* sA, int lda, const uint32_t* sB, int ldb,
    float (*acc)[NI][4], int wm, int wn, int grp, int qid)
{
#pragma unroll
    for (int ks = 0; ks < 32; ks += 8) {
        uint32_t a[MI][4], b[NI][2];
#pragma unroll
        for (int mi = 0; mi < MI; mi++) {
            const uint32_t* p0 = sA + (ks + qid)*lda + wm + mi*16 + grp;
            const uint32_t* p1 = p0 + 4*lda;
            a[mi][0] = p0[0]; a[mi][1] = p0[8]; a[mi][2] = p1[0]; a[mi][3] = p1[8];
        }
#pragma unroll
        for (int ni = 0; ni < NI; ni++) {
            const uint32_t* q0 = sB + (ks + qid)*ldb + wn + ni*8 + grp;
            b[ni][0] = q0[0]; b[ni][1] = q0[4*ldb];
        }
#pragma unroll
        for (int mi = 0; mi < MI; mi++)
#pragma unroll
            for (int ni = 0; ni < NI; ni++)
                mma8(acc[mi][ni], a[mi], b[ni]);
    }
}

// ----- A smem [m][k], B smem [n][k] ----------------------------------------
template<int MI, int NI>
static __device__ __forceinline__ void stage_mk_nk(
    const uint32_t* sA, int lda, const uint32_t* sB, int ldb,
    float (*acc)[NI][4], int wm, int wn, int grp, int qid)
{
#pragma unroll
    for (int ks = 0; ks < 32; ks += 8) {
        uint32_t a[MI][4], b[NI][2];
#pragma unroll
        for (int mi = 0; mi < MI; mi++) {
            const uint32_t* p0 = sA + (wm + mi*16 + grp)*lda + ks + qid;
            a[mi][0] = p0[0]; a[mi][1] = p0[8*lda]; a[mi][2] = p0[4]; a[mi][3] = p0[8*lda + 4];
        }
#pragma unroll
        for (int ni = 0; ni < NI; ni++) {
            const uint32_t* q0 = sB + (wn + ni*8 + grp)*ldb + ks + qid;
            b[ni][0] = q0[0]; b[ni][1] = q0[4];
        }
#pragma unroll
        for (int mi = 0; mi < MI; mi++)
#pragma unroll
            for (int ni = 0; ni < NI; ni++)
                mma8(acc[mi][ni], a[mi], b[ni]);
    }
}

// ===== projection body (double-buffered, cvt fills) ========================
#define PROJ_SMEM_W (2*64*36 + 2*32*136)
static __device__ __forceinline__ void proj_body(
    const float* __restrict__ W, const float* __restrict__ bias,
    const float* __restrict__ Xb, float* __restrict__ Ob, int o0, int n0,
    uint32_t* sm)
{
    uint32_t* sA = sm;
    uint32_t* sB = sm + 2*64*36;
    const int tid = threadIdx.x;
    const int lane = tid & 31, w = tid >> 5;
    const int grp = lane >> 2, qid = lane & 3;
    const int wm = (w & 1)*32, wn = (w >> 1)*32;
    float acc[2][4][4] = {};
    const int rA = tid >> 3,  cA = (tid & 7)*4;
    const int rB = tid >> 5,  cB = (tid & 31)*4;

#pragma unroll
    for (int jj = 0; jj < 2; jj++) {
        float4 v = *(const float4*)&W[(o0 + rA + jj*32)*CC + cA];
        *(uint4*)&sA[(rA + jj*32)*36 + cA] = cvt4(v);
    }
#pragma unroll
    for (int jj = 0; jj < 4; jj++) {
        float4 v = *(const float4*)&Xb[(size_t)(rB + jj*8)*TT + n0 + cB];
        *(uint4*)&sB[(rB + jj*8)*136 + cB] = cvt4(v);
    }
    __syncthreads();

    const int NK = CC/32;
    for (int k = 0; k < NK; k++) {
        float4 ra[2], rb[4];
        if (k + 1 < NK) {
            int k0 = (k + 1)*32;
#pragma unroll
            for (int jj = 0; jj < 2; jj++)
                ra[jj] = *(const float4*)&W[(o0 + rA + jj*32)*CC + k0 + cA];
#pragma unroll
            for (int jj = 0; jj < 4; jj++)
                rb[jj] = *(const float4*)&Xb[(size_t)(k0 + rB + jj*8)*TT + n0 + cB];
        }
        int cur = k & 1;
        stage_mk_kn<2,4>(sA + cur*64*36, 36, sB + cur*32*136, 136, 0, acc, wm, wn, grp, qid);
        if (k + 1 < NK) {
            int nx = cur ^ 1;
#pragma unroll
            for (int jj = 0; jj < 2; jj++)
                *(uint4*)&sA[nx*64*36 + (rA + jj*32)*36 + cA] = cvt4(ra[jj]);
#pragma unroll
            for (int jj = 0; jj < 4; jj++)
                *(uint4*)&sB[nx*32*136 + (rB + jj*8)*136 + cB] = cvt4(rb[jj]);
            __syncthreads();
        }
    }
#pragma unroll
    for (int mi = 0; mi < 2; mi++) {
        int r0 = o0 + wm + mi*16 + grp;
        float bb0 = bias[r0], bb1 = bias[r0 + 8];
#pragma unroll
        for (int ni = 0; ni < 4; ni++) {
            int c0 = n0 + wn + ni*8 + qid*2;
            Ob[(size_t)r0*TT + c0]       = acc[mi][ni][0] + bb0;
            Ob[(size_t)r0*TT + c0 + 1]   = acc[mi][ni][1] + bb0;
            Ob[(size_t)(r0+8)*TT + c0]   = acc[mi][ni][2] + bb1;
            Ob[(size_t)(r0+8)*TT + c0+1] = acc[mi][ni][3] + bb1;
        }
    }
}

__global__ void qkv_mma(const float* __restrict__ Wq, const float* __restrict__ bq,
                        const float* __restrict__ Wk, const float* __restrict__ bk,
                        const float* __restrict__ Wv, const float* __restrict__ bv,
                        const float* __restrict__ X,
                        float* __restrict__ Qo, float* __restrict__ Ko, float* __restrict__ Vo)
{
    extern __shared__ uint32_t sm[];
    const int sel = blockIdx.x / 3;
    const int o0  = (blockIdx.x % 3)*64;
    const int n0  = blockIdx.y*128;
    const int b   = blockIdx.z;
    const float* W    = (sel == 0) ? Wq : (sel == 1) ? Wk : Wv;
    const float* bias = (sel == 0) ? bq : (sel == 1) ? bk : bv;
    float* Out        = (sel == 0) ? Qo : (sel == 1) ? Ko : Vo;
    proj_body(W, bias, X + (size_t)b*CC*TT, Out + (size_t)b*CC*TT, o0, n0, sm);
}

__global__ void proj_mma(const float* __restrict__ W, const float* __restrict__ bias,
                         const float* __restrict__ X, float* __restrict__ Out)
{
    extern __shared__ uint32_t sm[];
    proj_body(W, bias, X + (size_t)blockIdx.z*CC*TT, Out + (size_t)blockIdx.z*CC*TT,
              blockIdx.x*64, blockIdx.y*128, sm);
}

// ------- rel logits: RL[bh,t,m] = scale * q[:,t] . erk[m,:], m=0..8 --------
__global__ void rel_logits_k(const float* __restrict__ Q, const float* __restrict__ erk)
{
    const int bh = blockIdx.y, b = bh / HH, h = bh % HH;
    const int t = blockIdx.x*256 + threadIdx.x;
    __shared__ float sE[9*96];
    for (int i = threadIdx.x; i < 9*96; i += 256) sE[i] = erk[i];
    __syncthreads();
    const float* q = Q + (size_t)(b*CC + h*DKK)*TT;
    float acc[9] = {};
    for (int d = 0; d < DKK; d++) {
        float qv = q[(size_t)d*TT + t];
#pragma unroll
        for (int m = 0; m < 9; m++) acc[m] += qv * sE[m*96 + d];
    }
    float* out = g_RL + ((size_t)bh*TT + t)*9;
    const float sc = relscale();
#pragma unroll
    for (int m = 0; m < 9; m++) out[m] = acc[m]*sc;
}

// ===== scores: S[t,s] = (q*sc)·k + band; writes S + per-chunk (max,sumexp) =
#define SCORES_SMEM_W (2*32*72 + 2*32*136 + 576 + 256 + 256)
__global__ void scores_mma(const float* __restrict__ Q, const float* __restrict__ Kk)
{
    extern __shared__ uint32_t sm[];
    uint32_t* sA = sm;
    uint32_t* sB = sm + 2*32*72;
    float* sRL = (float*)(sm + 2*32*72 + 2*32*136);   // [64][9]
    float* sMx = sRL + 576;                            // [64][4]
    float* sSm = sMx + 256;                            // [64][4]
    const int bh = blockIdx.z, b = bh >> 1, h = bh & 1;
    const float* q = Q  + (size_t)(b*CC + h*DKK)*TT;
    const float* k = Kk + (size_t)(b*CC + h*DKK)*TT;
    float* S = g_S + (size_t)bh*TT*TT;
    const int t0 = blockIdx.x*64, s0 = blockIdx.y*128;
    const int sy = blockIdx.y;

    const int tid = threadIdx.x;
    const int lane = tid & 31, w = tid >> 5;
    const int grp = lane >> 2, qid = lane & 3;
    const int wm = (w & 1)*32, wn = (w >> 1)*32;
    const int wnid = w >> 1;
    const float sc = relscale();
    float acc[2][4][4] = {};
    const int rA = tid >> 4, cA = (tid & 15)*4;
    const int rB = tid >> 5, cB = (tid & 31)*4;

    // band logits for this t block (contiguous copy)
    const float* rlg = g_RL + ((size_t)bh*TT + t0)*9;
    for (int i = tid; i < 576; i += 256) sRL[i] = rlg[i];

    auto ldq = [&](int k0, int jj) {
        float4 v = *(const float4*)&q[(size_t)(k0 + rA + jj*16)*TT + t0 + cA];
        v.x *= sc; v.y *= sc; v.z *= sc; v.w *= sc;
        return v;
    };
#pragma unroll
    for (int jj = 0; jj < 2; jj++)
        *(uint4*)&sA[(rA + jj*16)*72 + cA] = cvt4(ldq(0, jj));
#pragma unroll
    for (int jj = 0; jj < 4; jj++) {
        float4 v = *(const float4*)&k[(size_t)(rB + jj*8)*TT + s0 + cB];
        *(uint4*)&sB[(rB + jj*8)*136 + cB] = cvt4(v);
    }
    __syncthreads();

    const int NK = DKK/32;
    for (int kc = 0; kc < NK; kc++) {
        float4 ra[2], rb[4];
        if (kc + 1 < NK) {
            int k0 = (kc + 1)*32;
#pragma unroll
            for (int jj = 0; jj < 2; jj++) ra[jj] = ldq(k0, jj);
#pragma unroll
            for (int jj = 0; jj < 4; jj++)
                rb[jj] = *(const float4*)&k[(size_t)(k0 + rB + jj*8)*TT + s0 + cB];
        }
        int cur = kc & 1;
        stage_km_kn<2,4>(sA + cur*32*72, 72, sB + cur*32*136, 136, acc, wm, wn, grp, qid);
        if (kc + 1 < NK) {
            int nx = cur ^ 1;
#pragma unroll
            for (int jj = 0; jj < 2; jj++)
                *(uint4*)&sA[nx*32*72 + (rA + jj*16)*72 + cA] = cvt4(ra[jj]);
#pragma unroll
            for (int jj = 0; jj < 4; jj++)
                *(uint4*)&sB[nx*32*136 + (rB + jj*8)*136 + cB] = cvt4(rb[jj]);
            __syncthreads();
        }
    }

    // ---- epilogue: band add + store + per-row chunk (max, sumexp) ----
    float vv[2][4][4];
#pragma unroll
    for (int mi = 0; mi < 2; mi++) {
        int rl0 = wm + mi*16 + grp;      // local rows rl0, rl0+8
        int rl1 = rl0 + 8;
#pragma unroll
        for (int ni = 0; ni < 4; ni++) {
            int cl = wn + ni*8 + qid*2;
            int sg = s0 + cl;
#pragma unroll
            for (int e = 0; e < 2; e++) {
                float v0 = acc[mi][ni][e];
                int off0 = sg + e - (t0 + rl0);
                if (off0 >= -WW && off0 <= WW) v0 += sRL[rl0*9 + off0 + WW];
                vv[mi][ni][e] = v0;
                float v1 = acc[mi][ni][2 + e];
                int off1 = sg + e - (t0 + rl1);
                if (off1 >= -WW && off1 <= WW) v1 += sRL[rl1*9 + off1 + WW];
                vv[mi][ni][2 + e] = v1;
            }
            S[(size_t)(t0 + rl0)*TT + sg]     = vv[mi][ni][0];
            S[(size_t)(t0 + rl0)*TT + sg + 1] = vv[mi][ni][1];
            S[(size_t)(t0 + rl1)*TT + sg]     = vv[mi][ni][2];
            S[(size_t)(t0 + rl1)*TT + sg + 1] = vv[mi][ni][3];
        }
    }
    // per-row max over this thread's 8 cols, then over qid, then across warps
    float mx[2][2];
#pragma unroll
    for (int mi = 0; mi < 2; mi++) {
        mx[mi][0] = -1e30f; mx[mi][1] = -1e30f;
#pragma unroll
        for (int ni = 0; ni < 4; ni++) {
            mx[mi][0] = fmaxf(mx[mi][0], fmaxf(vv[mi][ni][0], vv[mi][ni][1]));
            mx[mi][1] = fmaxf(mx[mi][1], fmaxf(vv[mi][ni][2], vv[mi][ni][3]));
        }
#pragma unroll
        for (int r = 0; r < 2; r++) {
            mx[mi][r] = fmaxf(mx[mi][r], __shfl_xor_sync(0xffffffffu, mx[mi][r], 1));
            mx[mi][r] = fmaxf(mx[mi][r], __shfl_xor_sync(0xffffffffu, mx[mi][r], 2));
        }
    }
    if (qid == 0) {
#pragma unroll
        for (int mi = 0; mi < 2; mi++) {
            sMx[(wm + mi*16 + grp)*4 + wnid]     = mx[mi][0];
            sMx[(wm + mi*16 + grp + 8)*4 + wnid] = mx[mi][1];
        }
    }
    __syncthreads();
    float gs[2][2] = {};
#pragma unroll
    for (int mi = 0; mi < 2; mi++) {
        int rl0 = wm + mi*16 + grp;
        float m0 = fmaxf(fmaxf(sMx[rl0*4], sMx[rl0*4+1]), fmaxf(sMx[rl0*4+2], sMx[rl0*4+3]));
        float m1 = fmaxf(fmaxf(sMx[(rl0+8)*4], sMx[(rl0+8)*4+1]),
                         fmaxf(sMx[(rl0+8)*4+2], sMx[(rl0+8)*4+3]));
#pragma unroll
        for (int ni = 0; ni < 4; ni++) {
            gs[mi][0] += __expf(vv[mi][ni][0] - m0) + __expf(vv[mi][ni][1] - m0);
            gs[mi][1] += __expf(vv[mi][ni][2] - m1) + __expf(vv[mi][ni][3] - m1);
        }
#pragma unroll
        for (int r = 0; r < 2; r++) {
            gs[mi][r] += __shfl_xor_sync(0xffffffffu, gs[mi][r], 1);
            gs[mi][r] += __shfl_xor_sync(0xffffffffu, gs[mi][r], 2);
        }
    }
    if (qid == 0) {
#pragma unroll
        for (int mi = 0; mi < 2; mi++) {
            sSm[(wm + mi*16 + grp)*4 + wnid]     = gs[mi][0];
            sSm[(wm + mi*16 + grp + 8)*4 + wnid] = gs[mi][1];
        }
    }
    __syncthreads();
    if (tid < 64) {
        float m = fmaxf(fmaxf(sMx[tid*4], sMx[tid*4+1]), fmaxf(sMx[tid*4+2], sMx[tid*4+3]));
        float s = sSm[tid*4] + sSm[tid*4+1] + sSm[tid*4+2] + sSm[tid*4+3];
        size_t base = ((size_t)bh*TT + t0 + tid)*8 + sy;
        g_PM[base] = m;
        g_PS[base] = s;
    }
}

// ===== attn out: softmax-on-the-fly + PV + rel-v band; 96(d) x 128(t) =====
#define ATTN_SMEM_W (2*96*36 + 2*128*36 + 128*9 + 9*96 + 128 + 128)
__global__ void attnout_mma(const float* __restrict__ V, const float* __restrict__ erv)
{
    extern __shared__ uint32_t sm[];
    uint32_t* sA  = sm;                      // 2 * 96*36, [m=d][k=s]
    uint32_t* sB  = sm + 2*96*36;            // 2 * 128*36, [n=t][k=s]
    float*    sPb = (float*)(sm + 2*96*36 + 2*128*36);   // [128][9]
    float*    sE  = sPb + 128*9;                          // [9][96]
    float*    sMx = sE + 864;                             // [128]
    float*    sIv = sMx + 128;                            // [128]
    const int bh = blockIdx.y, b = bh >> 1, h = bh & 1;
    const float* p = g_S + (size_t)bh*TT*TT;
    const float* v = V   + (size_t)(b*CC + h*DKK)*TT;
    float*       a = g_A + (size_t)(b*CC + h*DKK)*TT;
    const int t0 = blockIdx.x*128;

    const int tid = threadIdx.x;
    const int lane = tid & 31, w = tid >> 5;
    const int grp = lane >> 2, qid = lane & 3;
    const int wm = (w & 1)*48, wn = (w >> 1)*32;
    float acc[3][4][4] = {};
    const int rT = tid >> 3, cT = (tid & 7)*4;

    // row stats: combine 8 chunk partials
    if (tid < 128) {
        size_t base = ((size_t)bh*TT + t0 + tid)*8;
        float pm[8], ps[8];
        float m = -1e30f;
#pragma unroll
        for (int j = 0; j < 8; j++) { pm[j] = g_PM[base + j]; ps[j] = g_PS[base + j]; m = fmaxf(m, pm[j]); }
        float s = 0.f;
#pragma unroll
        for (int j = 0; j < 8; j++) s += ps[j]*__expf(pm[j] - m);
        sMx[tid] = m;
        sIv[tid] = 1.f / s;
    }
    __syncthreads();

    auto pxf = [&](float4 s4, int row) {
        float mxv = sMx[row], iv = sIv[row];
        uint4 u;
        u.x = f2tf(__expf(s4.x - mxv)*iv);
        u.y = f2tf(__expf(s4.y - mxv)*iv);
        u.z = f2tf(__expf(s4.z - mxv)*iv);
        u.w = f2tf(__expf(s4.w - mxv)*iv);
        return u;
    };

    // band P + erv (once)
    for (int i = tid; i < 128*9; i += 256) {
        int tr = i / 9, m = i - tr*9;
        int s = t0 + tr + m - WW;
        sPb[tr*9 + m] = (s >= 0 && s < TT)
            ? __expf(p[(size_t)(t0 + tr)*TT + s] - sMx[tr])*sIv[tr] : 0.f;
    }
    for (int i = tid; i < 9*96; i += 256) sE[i] = erv[i];

#pragma unroll
    for (int jj = 0; jj < 3; jj++) {
        float4 vvv = *(const float4*)&v[(size_t)(rT + jj*32)*TT + cT];
        *(uint4*)&sA[(rT + jj*32)*36 + cT] = cvt4(vvv);
    }
#pragma unroll
    for (int jj = 0; jj < 4; jj++) {
        float4 pv = *(const float4*)&p[(size_t)(t0 + rT + jj*32)*TT + cT];
        *(uint4*)&sB[(rT + jj*32)*36 + cT] = pxf(pv, rT + jj*32);
    }
    __syncthreads();

    const int NK = TT/32;  // 32
    for (int kc = 0; kc < NK; kc++) {
        float4 ra[3], rb[4];
        if (kc + 1 < NK) {
            int s0 = (kc + 1)*32;
#pragma unroll
            for (int jj = 0; jj < 3; jj++)
                ra[jj] = *(const float4*)&v[(size_t)(rT + jj*32)*TT + s0 + cT];
#pragma unroll
            for (int jj = 0; jj < 4; jj++)
                rb[jj] = *(const float4*)&p[(size_t)(t0 + rT + jj*32)*TT + s0 + cT];
        }
        int cur = kc & 1;
        stage_mk_nk<3,4>(sA + cur*96*36, 36, sB + cur*128*36, 36, acc, wm, wn, grp, qid);
        if (kc + 1 < NK) {
            int nx = cur ^ 1;
#pragma unroll
            for (int jj = 0; jj < 3; jj++)
                *(uint4*)&sA[nx*96*36 + (rT + jj*32)*36 + cT] = cvt4(ra[jj]);
#pragma unroll
            for (int jj = 0; jj < 4; jj++)
                *(uint4*)&sB[nx*128*36 + (rT + jj*32)*36 + cT] = pxf(rb[jj], rT + jj*32);
            __syncthreads();
        }
    }
    // epilogue: add banded rel-v term and store
#pragma unroll
    for (int mi = 0; mi < 3; mi++) {
        int r0 = wm + mi*16 + grp;           // d rows r0, r0+8
        float e0[9], e1[9];
#pragma unroll
        for (int m = 0; m < 9; m++) { e0[m] = sE[m*96 + r0]; e1[m] = sE[m*96 + r0 + 8]; }
#pragma unroll
        for (int ni = 0; ni < 4; ni++) {
            int cl = wn + ni*8 + qid*2;      // local t
            float s00 = 0.f, s01 = 0.f, s10 = 0.f, s11 = 0.f;
#pragma unroll
            for (int m = 0; m < 9; m++) {
                float p0 = sPb[cl*9 + m], p1 = sPb[(cl+1)*9 + m];
                s00 += p0*e0[m]; s01 += p1*e0[m];
                s10 += p0*e1[m]; s11 += p1*e1[m];
            }
            int c0 = t0 + cl;
            a[(size_t)r0*TT + c0]       = acc[mi][ni][0] + s00;
            a[(size_t)r0*TT + c0 + 1]   = acc[mi][ni][1] + s01;
            a[(size_t)(r0+8)*TT + c0]   = acc[mi][ni][2] + s10;
            a[(size_t)(r0+8)*TT + c0+1] = acc[mi][ni][3] + s11;
        }
    }
}

// ===== conv3 v2 (conv1): 128(f) x 128(t), cp.async weights =================
#define CONV1_SMEM_W (2*3*128*36 + 2*32*136)
__global__ void __launch_bounds__(256, 1)
conv3_mma_128(const float* __restrict__ Wt, const float* __restrict__ bias,
              const float* __restrict__ X, float* __restrict__ Out,
              int Cout, int Cin, int do_relu)
{
    extern __shared__ uint32_t sm[];
    uint32_t* sA = sm;                 // 2 × 3 × 128*36
    uint32_t* sB = sm + 2*3*128*36;    // 2 × 32*136 slab; col = t - t0 + 4
    const int o0 = blockIdx.x*128, t0 = blockIdx.y*128, b = blockIdx.z;
    const float* Xb = X + (size_t)b*Cin*TT;
    float* Ob = Out + (size_t)b*Cout*TT;

    const int tid = threadIdx.x;
    const int lane = tid & 31, w = tid >> 5;
    const int grp = lane >> 2, qid = lane & 3;
    const int wm = (w & 3)*32, wn = (w >> 2)*64;
    float acc[2][8][4] = {};
    const int rS = tid >> 5, cS = (tid & 31)*4;
    const int er = tid >> 1, es = tid & 1;

    auto fill_slab = [&](uint32_t* dst, int c0) {
#pragma unroll
        for (int jj = 0; jj < 4; jj++) {
            float4 v = *(const float4*)&Xb[(size_t)(c0 + rS + jj*8)*TT + t0 + cS];
            *(uint4*)&dst[(rS + jj*8)*136 + 4 + cS] = cvt4(v);
        }
        if (tid < 64) {
            int t = es ? (t0 + 128) : (t0 - 1);
            int col = es ? 132 : 3;
            float vv = (t >= 0 && t < TT) ? Xb[(size_t)(c0 + er)*TT + t] : 0.f;
            dst[er*136 + col] = f2tf(vv);
        }
    };
    auto cpa_w = [&](uint32_t* dst, int c0) {
#pragma unroll
        for (int jj = 0; jj < 12; jj++) {
            int i = tid + jj*256;
            int j = i >> 10, r = (i >> 3) & 127, c4 = (i & 7)*4;
            cpa16(&dst[j*128*36 + r*36 + c4],
                  &Wt[((size_t)j*Cout + o0 + r)*Cin + c0 + c4]);
        }
    };

    cpa_w(sA, 0); CP_COMMIT;
    fill_slab(sB, 0);
    CP_WAIT0;
    __syncthreads();

    const int NK = Cin/32;
    for (int kc = 0; kc < NK; kc++) {
        int cur = kc & 1, nx = cur ^ 1;
        float4 rx[4]; float re = 0.f;
        if (kc + 1 < NK) {
            int c0 = (kc + 1)*32;
            cpa_w(sA + nx*3*128*36, c0);       // async, overlaps mma below
            CP_COMMIT;
#pragma unroll
            for (int jj = 0; jj < 4; jj++)
                rx[jj] = *(const float4*)&Xb[(size_t)(c0 + rS + jj*8)*TT + t0 + cS];
            if (tid < 64) {
                int t = es ? (t0 + 128) : (t0 - 1);
                re = (t >= 0 && t < TT) ? Xb[(size_t)(c0 + er)*TT + t] : 0.f;
            }
        }
#pragma unroll
        for (int j = 0; j < 3; j++)
            stage_mk_kn<2,8>(sA + cur*3*128*36 + j*128*36, 36, sB + cur*32*136, 136,
                             j + 3, acc, wm, wn, grp, qid);
        if (kc + 1 < NK) {
#pragma unroll
            for (int jj = 0; jj < 4; jj++)
                *(uint4*)&sB[nx*32*136 + (rS + jj*8)*136 + 4 + cS] = cvt4(rx[jj]);
            if (tid < 64) {
                int col = es ? 132 : 3;
                sB[nx*32*136 + er*136 + col] = f2tf(re);
            }
            CP_WAIT0;
            __syncthreads();
        }
    }
#pragma unroll
    for (int mi = 0; mi < 2; mi++) {
        int r0 = o0 + wm + mi*16 + grp;
        float bb0 = bias[r0], bb1 = bias[r0 + 8];
#pragma unroll
        for (int ni = 0; ni < 8; ni++) {
            int c0 = t0 + wn + ni*8 + qid*2;
            float v0 = acc[mi][ni][0] + bb0;
            float v1 = acc[mi][ni][1] + bb0;
            float v2 = acc[mi][ni][2] + bb1;
            float v3 = acc[mi][ni][3] + bb1;
            if (do_relu) { v0 = fmaxf(v0, 0.f); v1 = fmaxf(v1, 0.f);
                           v2 = fmaxf(v2, 0.f); v3 = fmaxf(v3, 0.f); }
            Ob[(size_t)r0*TT + c0]       = v0;
            Ob[(size_t)r0*TT + c0 + 1]   = v1;
            Ob[(size_t)(r0+8)*TT + c0]   = v2;
            Ob[(size_t)(r0+8)*TT + c0+1] = v3;
        }
    }
}

// ===== conv3 v3 (conv2): 96(f) x 128(t), MI=3, cp.async weights ============
#define CONV2_SMEM_W (2*3*96*36 + 2*32*136)
__global__ void __launch_bounds__(256, 1)
conv3_mma_96(const float* __restrict__ Wt, const float* __restrict__ bias,
             const float* __restrict__ X, float* __restrict__ Out,
             int Cout, int Cin, int do_relu)
{
    extern __shared__ uint32_t sm[];
    uint32_t* sA = sm;                 // 2 × 3 × 96*36
    uint32_t* sB = sm + 2*3*96*36;     // 2 × 32*136 slab; col = t - t0 + 4
    const int o0 = blockIdx.x*96, t0 = blockIdx.y*128, b = blockIdx.z;
    const float* Xb = X + (size_t)b*Cin*TT;
    float* Ob = Out + (size_t)b*Cout*TT;

    const int tid = threadIdx.x;
    const int lane = tid & 31, w = tid >> 5;
    const int grp = lane >> 2, qid = lane & 3;
    const int wm = (w & 1)*48, wn = (w >> 1)*32;
    float acc[3][4][4] = {};
    const int rS = tid >> 5, cS = (tid & 31)*4;
    const int er = tid >> 1, es = tid & 1;

    auto fill_slab = [&](uint32_t* dst, int c0) {
#pragma unroll
        for (int jj = 0; jj < 4; jj++) {
            float4 v = *(const float4*)&Xb[(size_t)(c0 + rS + jj*8)*TT + t0 + cS];
            *(uint4*)&dst[(rS + jj*8)*136 + 4 + cS] = cvt4(v);
        }
        if (tid < 64) {
            int t = es ? (t0 + 128) : (t0 - 1);
            int col = es ? 132 : 3;
            float vv = (t >= 0 && t < TT) ? Xb[(size_t)(c0 + er)*TT + t] : 0.f;
            dst[er*136 + col] = f2tf(vv);
        }
    };
    auto cpa_w = [&](uint32_t* dst, int c0) {
#pragma unroll
        for (int jj = 0; jj < 9; jj++) {          // 3*96*8 = 2304 uint4
            int i = tid + jj*256;
            int j = i / 768, rem = i - j*768;
            int r = rem >> 3, c4 = (rem & 7)*4;
            cpa16(&dst[j*96*36 + r*36 + c4],
                  &Wt[((size_t)j*Cout + o0 + r)*Cin + c0 + c4]);
        }
    };

    cpa_w(sA, 0); CP_COMMIT;
    fill_slab(sB, 0);
    CP_WAIT0;
    __syncthreads();

    const int NK = Cin/32;     // 24
    for (int kc = 0; kc < NK; kc++) {
        int cur = kc & 1, nx = cur ^ 1;
        float4 rx[4]; float re = 0.f;
        if (kc + 1 < NK) {
            int c0 = (kc + 1)*32;
            cpa_w(sA + nx*3*96*36, c0);        // async, overlaps mma below
            CP_COMMIT;
#pragma unroll
            for (int jj = 0; jj < 4; jj++)
                rx[jj] = *(const float4*)&Xb[(size_t)(c0 + rS + jj*8)*TT + t0 + cS];
            if (tid < 64) {
                int t = es ? (t0 + 128) : (t0 - 1);
                re = (t >= 0 && t < TT) ? Xb[(size_t)(c0 + er)*TT + t] : 0.f;
            }
        }
#pragma unroll
        for (int j = 0; j < 3; j++)
            stage_mk_kn<3,4>(sA + cur*3*96*36 + j*96*36, 36, sB + cur*32*136, 136,
                             j + 3, acc, wm, wn, grp, qid);
        if (kc + 1 < NK) {
#pragma unroll
            for (int jj = 0; jj < 4; jj++)
                *(uint4*)&sB[nx*32*136 + (rS + jj*8)*136 + 4 + cS] = cvt4(rx[jj]);
            if (tid < 64) {
                int col = es ? 132 : 3;
                sB[nx*32*136 + er*136 + col] = f2tf(re);
            }
            CP_WAIT0;
            __syncthreads();
        }
    }
#pragma unroll
    for (int mi = 0; mi < 3; mi++) {
        int r0 = o0 + wm + mi*16 + grp;
        float bb0 = bias[r0], bb1 = bias[r0 + 8];
#pragma unroll
        for (int ni = 0; ni < 4; ni++) {
            int c0 = t0 + wn + ni*8 + qid*2;
            float v0 = acc[mi][ni][0] + bb0;
            float v1 = acc[mi][ni][1] + bb0;
            float v2 = acc[mi][ni][2] + bb1;
            float v3 = acc[mi][ni][3] + bb1;
            if (do_relu) { v0 = fmaxf(v0, 0.f); v1 = fmaxf(v1, 0.f);
                           v2 = fmaxf(v2, 0.f); v3 = fmaxf(v3, 0.f); }
            Ob[(size_t)r0*TT + c0]       = v0;
            Ob[(size_t)r0*TT + c0 + 1]   = v1;
            Ob[(size_t)(r0+8)*TT + c0]   = v2;
            Ob[(size_t)(r0+8)*TT + c0+1] = v3;
        }
    }
}

// ---- weight transpose+round: wt[l][j][f][c] = tf32(w[l][f][c][j]) ----------
__global__ void round_transpose_w(const float* __restrict__ w, float* __restrict__ wt,
                                  int Cout, int Cin)
{
    int idx = blockIdx.x*256 + threadIdx.x;
    int per = Cout*Cin*3;
    if (idx >= LL*per) return;
    int l = idx / per;
    int rem = idx - l*per;
    int j = rem / (Cout*Cin);
    int r2 = rem - j*Cout*Cin;
    int f = r2 / Cin, c = r2 - f*Cin;
    wt[idx] = __uint_as_float(f2tf(w[((size_t)l*Cout*Cin + (size_t)f*Cin + c)*3 + j]));
}

// --------- add + channel LayerNorm: Out = LN_c(X+Y)*g + beta ---------------
__global__ void add_ln_k(const float* __restrict__ X, const float* __restrict__ Y,
                         const float* __restrict__ g, const float* __restrict__ be,
                         float* __restrict__ Out)
{
    int idx = blockIdx.x*blockDim.x + threadIdx.x;
    if (idx >= BB*TT) return;
    int b = idx / TT, t = idx % TT;
    const float* xp = X + (size_t)b*CC*TT + t;
    const float* yp = Y + (size_t)b*CC*TT + t;
    float s = 0.f, sq = 0.f;
#pragma unroll 8
    for (int c = 0; c < CC; c++) {
        float v = xp[(size_t)c*TT] + yp[(size_t)c*TT];
        s += v; sq += v*v;
    }
    const float invC = 1.f / CC;
    float mean = s*invC;
    float var  = sq*invC - mean*mean;
    float rstd = rsqrtf(var + 1e-5f);
    float* op = Out + (size_t)b*CC*TT + t;
#pragma unroll 8
    for (int c = 0; c < CC; c++) {
        float v = xp[(size_t)c*TT] + yp[(size_t)c*TT];
        op[(size_t)c*TT] = (v - mean)*rstd*g[c] + be[c];
    }
}

// ---------------------------- host orchestration ---------------------------
extern "C" void kernel_launch(void* const* d_in, const int* in_sizes, int n_in,
                              void* d_out, int out_size)
{
    (void)in_sizes; (void)n_in; (void)out_size;
    const float* x_in = (const float*)d_in[0];
    const float* Wq = (const float*)d_in[2];
    const float* bq = (const float*)d_in[3];
    const float* Wk = (const float*)d_in[4];
    const float* bk = (const float*)d_in[5];
    const float* Wv = (const float*)d_in[6];
    const float* bv = (const float*)d_in[7];
    const float* Wo = (const float*)d_in[8];
    const float* bo = (const float*)d_in[9];
    const float* erk = (const float*)d_in[10];
    const float* erv = (const float*)d_in[11];
    const float* ln1g = (const float*)d_in[12];
    const float* ln1b = (const float*)d_in[13];
    const float* w1 = (const float*)d_in[14];
    const float* b1 = (const float*)d_in[15];
    const float* w2 = (const float*)d_in[16];
    const float* b2 = (const float*)d_in[17];
    const float* ln2g = (const float*)d_in[18];
    const float* ln2b = (const float*)d_in[19];

    float *X, *Q, *K, *V, *A, *Y, *W1t, *W2t, *Hf;
    cudaGetSymbolAddress((void**)&X,  g_X);
    cudaGetSymbolAddress((void**)&Q,  g_Q);
    cudaGetSymbolAddress((void**)&K,  g_K);
    cudaGetSymbolAddress((void**)&V,  g_V);
    cudaGetSymbolAddress((void**)&A,  g_A);
    cudaGetSymbolAddress((void**)&Y,  g_Y);
    cudaGetSymbolAddress((void**)&W1t, g_W1t);
    cudaGetSymbolAddress((void**)&W2t, g_W2t);
    cudaGetSymbolAddress((void**)&Hf, g_Hf);

    const int PROJ_SMEM   = PROJ_SMEM_W*4;
    const int SCORES_SMEM = SCORES_SMEM_W*4;
    const int ATTN_SMEM   = ATTN_SMEM_W*4;
    const int CONV1_SMEM  = CONV1_SMEM_W*4;
    const int CONV2_SMEM  = CONV2_SMEM_W*4;
    cudaFuncSetAttribute(qkv_mma,    cudaFuncAttributeMaxDynamicSharedMemorySize, PROJ_SMEM);
    cudaFuncSetAttribute(proj_mma,   cudaFuncAttributeMaxDynamicSharedMemorySize, PROJ_SMEM);
    cudaFuncSetAttribute(scores_mma, cudaFuncAttributeMaxDynamicSharedMemorySize, SCORES_SMEM);
    cudaFuncSetAttribute(attnout_mma,cudaFuncAttributeMaxDynamicSharedMemorySize, ATTN_SMEM);
    cudaFuncSetAttribute(conv3_mma_128, cudaFuncAttributeMaxDynamicSharedMemorySize, CONV1_SMEM);
    cudaFuncSetAttribute(conv3_mma_96,  cudaFuncAttributeMaxDynamicSharedMemorySize, CONV2_SMEM);

    // one-time weight transpose + tf32 pre-round
    {
        int tot1 = LL*FCC*CC*3;
        round_transpose_w<<<(tot1 + 255)/256, 256>>>(w1, W1t, FCC, CC);
        int tot2 = LL*CC*FCC*3;
        round_transpose_w<<<(tot2 + 255)/256, 256>>>(w2, W2t, CC, FCC);
    }

    const dim3 gqkv(9, TT/128, BB);
    const dim3 gproj(CC/64, TT/128, BB);
    const dim3 gscore(TT/64, TT/128, BB*HH);
    const dim3 grel(TT/256, BB*HH);
    const dim3 gao(TT/128, BB*HH);
    const dim3 gc1(FCC/128, TT/128, BB);
    const dim3 gc2(CC/96, TT/128, BB);
    const int lnBlocks = (BB*TT + 255)/256;

    for (int i = 0; i < LL; i++) {
        const float* xcur = (i == 0) ? x_in : X;
        qkv_mma<<<gqkv, 256, PROJ_SMEM>>>(Wq + (size_t)i*CC*CC, bq + i*CC,
                                          Wk + (size_t)i*CC*CC, bk + i*CC,
                                          Wv + (size_t)i*CC*CC, bv + i*CC,
                                          xcur, Q, K, V);
        rel_logits_k<<<grel, 256>>>(Q, erk + (size_t)i*9*DKK);
        scores_mma<<<gscore, 256, SCORES_SMEM>>>(Q, K);
        attnout_mma<<<gao, 256, ATTN_SMEM>>>(V, erv + (size_t)i*9*DKK);
        proj_mma<<<gproj, 256, PROJ_SMEM>>>(Wo + (size_t)i*CC*CC, bo + i*CC, A, Y);
        add_ln_k<<<lnBlocks, 256>>>(xcur, Y, ln1g + i*CC, ln1b + i*CC, X);
        conv3_mma_128<<<gc1, 256, CONV1_SMEM>>>(W1t + (size_t)i*3*FCC*CC, b1 + i*FCC,
                                                X, Hf, FCC, CC, 1);
        conv3_mma_96<<<gc2, 256, CONV2_SMEM>>>(W2t + (size_t)i*3*CC*FCC, b2 + i*CC,
                                               Hf, Y, CC, FCC, 0);
        add_ln_k<<<lnBlocks, 256>>>(X, Y, ln2g + i*CC, ln2b + i*CC,
                                    (i == LL-1) ? (float*)d_out : X);
    }
}